// round 3
// baseline (speedup 1.0000x reference)
#include <cuda_runtime.h>
#include <math.h>
#include <stdint.h>

// Problem constants
#define T  8192   // tokens = B*S
#define DM 1024   // model dim
#define EM 8      // experts
#define HM 4096   // hidden dim

// GEMM tiling (both FFN kernels): BM=128, BN=128, BK=16, 8 warps (2x4), warp tile 64x32
#define BM 128
#define BN 128
#define BK 16
#define ASTR 20    // sA row stride (floats): conflict-free frag loads
#define BSTR 136   // sB row stride (floats): conflict-free frag loads
#define NSTG 3     // pipeline stages

#define SA_ELEMS (BM * ASTR)          // 2560 floats / stage
#define SB_ELEMS (BK * BSTR)          // 2176 floats / stage
#define SMEM1_BYTES (NSTG * (SA_ELEMS + SB_ELEMS) * 4 + 512)
#define SMEM2_BYTES (NSTG * (SA_ELEMS + SB_ELEMS) * 4 + 1024)

// Device scratch (static device arrays: allowed; cudaMalloc is not)
__device__ int   g_count[EM];
__device__ int   g_tok[EM * T];
__device__ float g_gate[EM * T];
__device__ float g_xt[T * DM];           // tf32-rounded x
__device__ float g_wg[EM * DM * HM];     // tf32-rounded weights
__device__ float g_wu[EM * DM * HM];
__device__ float g_wd[EM * HM * DM];
__device__ float g_h[EM * T * HM];       // tf32-rounded hidden activations

// ---------------------------------------------------------------------------
// helpers
// ---------------------------------------------------------------------------
__device__ __forceinline__ float f2tf32f(float x) {
    uint32_t r;
    asm("cvt.rna.tf32.f32 %0, %1;" : "=r"(r) : "f"(x));
    return __uint_as_float(r);
}

__device__ __forceinline__ void mma_tf32(float d[4], const uint32_t a[4], const uint32_t b[2]) {
    asm volatile(
        "mma.sync.aligned.m16n8k8.row.col.f32.tf32.tf32.f32 "
        "{%0,%1,%2,%3}, {%4,%5,%6,%7}, {%8,%9}, {%0,%1,%2,%3};"
        : "+f"(d[0]), "+f"(d[1]), "+f"(d[2]), "+f"(d[3])
        : "r"(a[0]), "r"(a[1]), "r"(a[2]), "r"(a[3]),
          "r"(b[0]), "r"(b[1]));
}

__device__ __forceinline__ void cp16(float* smem_ptr, const float* gptr, bool valid) {
    uint32_t sa = (uint32_t)__cvta_generic_to_shared(smem_ptr);
    int sz = valid ? 16 : 0;
    asm volatile("cp.async.cg.shared.global [%0], [%1], 16, %2;"
                 :: "r"(sa), "l"(gptr), "r"(sz));
}
__device__ __forceinline__ void cp_commit() { asm volatile("cp.async.commit_group;"); }
template <int N>
__device__ __forceinline__ void cp_wait() { asm volatile("cp.async.wait_group %0;" :: "n"(N)); }

// ---------------------------------------------------------------------------
// zero output + round x to tf32 + zero counters (float4 per thread)
// ---------------------------------------------------------------------------
__global__ void k_zero_round(float4* __restrict__ out, const float4* __restrict__ x,
                             float4* __restrict__ xt, int n4) {
    int i = blockIdx.x * blockDim.x + threadIdx.x;
    if (i < n4) {
        out[i] = make_float4(0.f, 0.f, 0.f, 0.f);
        float4 v = x[i];
        v.x = f2tf32f(v.x); v.y = f2tf32f(v.y);
        v.z = f2tf32f(v.z); v.w = f2tf32f(v.w);
        xt[i] = v;
    }
    if (i < EM) g_count[i] = 0;
}

// round a weight tensor into scratch
__global__ void k_round4(const float4* __restrict__ src, float4* __restrict__ dst, int n4) {
    int i = blockIdx.x * blockDim.x + threadIdx.x;
    if (i < n4) {
        float4 v = src[i];
        v.x = f2tf32f(v.x); v.y = f2tf32f(v.y);
        v.z = f2tf32f(v.z); v.w = f2tf32f(v.w);
        dst[i] = v;
    }
}

// ---------------------------------------------------------------------------
// router: one warp per token. logits = x @ Wr + br ; top-2 ; softmax(2)
// ---------------------------------------------------------------------------
__global__ void k_router(const float* __restrict__ x,
                         const float* __restrict__ Wr,
                         const float* __restrict__ br) {
    int t    = blockIdx.x * (blockDim.x >> 5) + (threadIdx.x >> 5);
    int lane = threadIdx.x & 31;
    if (t >= T) return;

    const float* xr = x + (size_t)t * DM;
    float acc[EM];
#pragma unroll
    for (int e = 0; e < EM; e++) acc[e] = 0.0f;

    for (int d = lane; d < DM; d += 32) {
        float xv = xr[d];
        const float4 w0 = *(const float4*)(Wr + (size_t)d * EM);
        const float4 w1 = *(const float4*)(Wr + (size_t)d * EM + 4);
        acc[0] += xv * w0.x; acc[1] += xv * w0.y;
        acc[2] += xv * w0.z; acc[3] += xv * w0.w;
        acc[4] += xv * w1.x; acc[5] += xv * w1.y;
        acc[6] += xv * w1.z; acc[7] += xv * w1.w;
    }
#pragma unroll
    for (int e = 0; e < EM; e++) {
#pragma unroll
        for (int o = 16; o > 0; o >>= 1)
            acc[e] += __shfl_xor_sync(0xffffffffu, acc[e], o);
    }

    if (lane == 0) {
        float v[EM];
#pragma unroll
        for (int e = 0; e < EM; e++) v[e] = acc[e] + br[e];

        int b0 = 0; float m0 = v[0];
#pragma unroll
        for (int e = 1; e < EM; e++) if (v[e] > m0) { m0 = v[e]; b0 = e; }
        int b1 = -1; float m1 = -3.4e38f;
#pragma unroll
        for (int e = 0; e < EM; e++) {
            if (e == b0) continue;
            if (v[e] > m1) { m1 = v[e]; b1 = e; }
        }
        float p0 = 1.0f / (1.0f + expf(m1 - m0));  // softmax over {m0, m1}
        float p1 = 1.0f - p0;

        int pos = atomicAdd(&g_count[b0], 1);
        g_tok[b0 * T + pos] = t;  g_gate[b0 * T + pos] = p0;
        pos = atomicAdd(&g_count[b1], 1);
        g_tok[b1 * T + pos] = t;  g_gate[b1 * T + pos] = p1;
    }
}

// ---------------------------------------------------------------------------
// shared compute step: one BK=16 k-tile, 64x32 warp tiles, no cvt (pre-rounded)
// ---------------------------------------------------------------------------
#define SAI(st, r, c) sA[(st) * SA_ELEMS + (r) * ASTR + (c)]
#define SBI(st, k, c) sB[(st) * SB_ELEMS + (k) * BSTR + (c)]

__device__ __forceinline__ void gemm_step(
    const float* __restrict__ sA, const float* __restrict__ sB, int st,
    int wm, int wn, int g, int tq, float cc[4][4][4]) {
#pragma unroll
    for (int kk = 0; kk < BK; kk += 8) {
        uint32_t af[4][4];
#pragma unroll
        for (int im = 0; im < 4; im++) {
            int r = wm + im * 16 + g;
            af[im][0] = __float_as_uint(SAI(st, r,     kk + tq));
            af[im][1] = __float_as_uint(SAI(st, r + 8, kk + tq));
            af[im][2] = __float_as_uint(SAI(st, r,     kk + tq + 4));
            af[im][3] = __float_as_uint(SAI(st, r + 8, kk + tq + 4));
        }
#pragma unroll
        for (int in = 0; in < 4; in++) {
            int c = wn + in * 8 + g;
            uint32_t bf[2] = { __float_as_uint(SBI(st, kk + tq,     c)),
                               __float_as_uint(SBI(st, kk + tq + 4, c)) };
#pragma unroll
            for (int im = 0; im < 4; im++)
                mma_tf32(cc[im][in], af[im], bf);
        }
    }
}

// ---------------------------------------------------------------------------
// phase 1: h = silu(x@Wg + bg) * (x@Wu + bu)
// B-tile: 128 smem cols = 64 logical cols; tile cols 8q..8q+3 <- Wg, 8q+4..8q+7 <- Wu
// grid: (T/BM, HM/64, EM), 256 threads. 3-stage cp.async, 1 sync per k-tile.
// ---------------------------------------------------------------------------
__global__ __launch_bounds__(256) void k_ffn1(
    const float* __restrict__ bg, const float* __restrict__ bu) {

    const int e      = blockIdx.z;
    const int cnt    = g_count[e];
    const int m_base = blockIdx.x * BM;
    if (m_base >= cnt) return;
    const int n_base = blockIdx.y * 64;   // logical H columns

    extern __shared__ float smem[];
    float* sA   = smem;
    float* sB   = smem + NSTG * SA_ELEMS;
    int*   sTok = (int*)(sB + NSTG * SB_ELEMS);

    const int tid  = threadIdx.x;
    const int warp = tid >> 5, lane = tid & 31;
    const int g    = lane >> 2, tq  = lane & 3;
    const int wm   = (warp & 1) * 64;
    const int wn   = (warp >> 1) * 32;

    if (tid < BM) {
        int r = m_base + tid;
        sTok[tid] = (r < cnt) ? g_tok[e * T + r] : 0;
    }
    __syncthreads();   // gathered A loads read sTok

    float cc[4][4][4];
#pragma unroll
    for (int a = 0; a < 4; a++)
#pragma unroll
        for (int b = 0; b < 4; b++)
#pragma unroll
            for (int c = 0; c < 4; c++) cc[a][b][c] = 0.0f;

    const float* wBg = g_wg + (size_t)e * DM * HM + n_base;
    const float* wBu = g_wu + (size_t)e * DM * HM + n_base;

    auto load_tiles = [&](int st, int k0) {
#pragma unroll
        for (int j = 0; j < 2; j++) {          // A: 128x16 gathered rows
            int idx = tid + j * 256;
            int row = idx >> 2;
            int c4  = (idx & 3) << 2;
            cp16(&SAI(st, row, c4), g_xt + (size_t)sTok[row] * DM + k0 + c4, true);
        }
#pragma unroll
        for (int j = 0; j < 2; j++) {          // B: 16x128 interleaved Wg/Wu
            int idx  = tid + j * 256;
            int kr   = idx >> 5;
            int c4   = (idx & 31) << 2;
            int q    = c4 >> 3;
            const float* src = ((c4 >> 2) & 1) ? wBu : wBg;
            cp16(&SBI(st, kr, c4), src + (size_t)(k0 + kr) * HM + 4 * q, true);
        }
        cp_commit();
    };

    load_tiles(0, 0);
    load_tiles(1, BK);
    const int KT = DM / BK;   // 64
    for (int kt = 0; kt < KT; kt++) {
        if (kt + 2 < KT) cp_wait<1>(); else cp_wait<0>();
        __syncthreads();
        if (kt + 2 < KT) load_tiles((kt + 2) % NSTG, (kt + 2) * BK);
        gemm_step(sA, sB, kt % NSTG, wm, wn, g, tq, cc);
    }

    // epilogue: bias (own half), shuffle-exchange g<->u, silu, store tf32 h
    float* hb = g_h + (size_t)e * T * HM;
    const float* bge = bg + (size_t)e * HM;
    const float* bue = bu + (size_t)e * HM;
    const int tt = tq & 1;
    const bool is_g = (tq < 2);
#pragma unroll
    for (int im = 0; im < 4; im++) {
        int r0 = m_base + wm + im * 16 + g;
#pragma unroll
        for (int in = 0; in < 4; in++) {
            int q   = (wn + 8 * in) >> 3;
            int nl0 = n_base + 4 * q + 2 * tt;          // my 2 logical cols
            float bia0 = is_g ? bge[nl0]     : bue[nl0];
            float bia1 = is_g ? bge[nl0 + 1] : bue[nl0 + 1];
            float v0 = cc[im][in][0] + bia0, v1 = cc[im][in][1] + bia1;
            float v2 = cc[im][in][2] + bia0, v3 = cc[im][in][3] + bia1;
            float o0 = __shfl_xor_sync(0xffffffffu, v0, 2);
            float o1 = __shfl_xor_sync(0xffffffffu, v1, 2);
            float o2 = __shfl_xor_sync(0xffffffffu, v2, 2);
            float o3 = __shfl_xor_sync(0xffffffffu, v3, 2);
            if (is_g) {
                // own = gate, other = up
                if (r0 < cnt) {
                    float2 hv;
                    hv.x = f2tf32f(v0 / (1.0f + expf(-v0)) * o0);
                    hv.y = f2tf32f(v1 / (1.0f + expf(-v1)) * o1);
                    *(float2*)(hb + (size_t)r0 * HM + nl0) = hv;
                }
                if (r0 + 8 < cnt) {
                    float2 hv;
                    hv.x = f2tf32f(v2 / (1.0f + expf(-v2)) * o2);
                    hv.y = f2tf32f(v3 / (1.0f + expf(-v3)) * o3);
                    *(float2*)(hb + (size_t)(r0 + 8) * HM + nl0) = hv;
                }
            }
        }
    }
}

// ---------------------------------------------------------------------------
// phase 2: out[tok] += gate * (h @ Wd + bd)
// grid: (T/BM, DM/BN, EM), 256 threads. 3-stage cp.async, 1 sync per k-tile.
// ---------------------------------------------------------------------------
__global__ __launch_bounds__(256) void k_ffn2(
    const float* __restrict__ bd, float* __restrict__ out) {

    const int e      = blockIdx.z;
    const int cnt    = g_count[e];
    const int m_base = blockIdx.x * BM;
    if (m_base >= cnt) return;
    const int n_base = blockIdx.y * BN;

    extern __shared__ float smem[];
    float* sA    = smem;
    float* sB    = smem + NSTG * SA_ELEMS;
    int*   sTok  = (int*)(sB + NSTG * SB_ELEMS);
    float* sGate = (float*)(sTok + BM);

    const int tid  = threadIdx.x;
    const int warp = tid >> 5, lane = tid & 31;
    const int g    = lane >> 2, tq  = lane & 3;
    const int wm   = (warp & 1) * 64;
    const int wn   = (warp >> 1) * 32;

    if (tid < BM) {
        int r = m_base + tid;
        sTok[tid]  = (r < cnt) ? g_tok[e * T + r]  : 0;
        sGate[tid] = (r < cnt) ? g_gate[e * T + r] : 0.0f;
    }
    // A loads below use slot rows, not sTok; epilogue reads sTok after later syncs

    float cc[4][4][4];
#pragma unroll
    for (int a = 0; a < 4; a++)
#pragma unroll
        for (int b = 0; b < 4; b++)
#pragma unroll
            for (int c = 0; c < 4; c++) cc[a][b][c] = 0.0f;

    const float* hb = g_h + (size_t)e * T * HM;
    const float* wB = g_wd + (size_t)e * HM * DM + n_base;

    auto load_tiles = [&](int st, int k0) {
#pragma unroll
        for (int j = 0; j < 2; j++) {          // A: 128x16 slot rows (zfill past cnt)
            int idx = tid + j * 256;
            int row = idx >> 2;
            int c4  = (idx & 3) << 2;
            bool v  = (m_base + row) < cnt;
            cp16(&SAI(st, row, c4), hb + (size_t)(m_base + row) * HM + k0 + c4, v);
        }
#pragma unroll
        for (int j = 0; j < 2; j++) {          // B: 16x128
            int idx = tid + j * 256;
            int kr  = idx >> 5;
            int c4  = (idx & 31) << 2;
            cp16(&SBI(st, kr, c4), wB + (size_t)(k0 + kr) * DM + c4, true);
        }
        cp_commit();
    };

    load_tiles(0, 0);
    load_tiles(1, BK);
    const int KT = HM / BK;   // 256
    for (int kt = 0; kt < KT; kt++) {
        if (kt + 2 < KT) cp_wait<1>(); else cp_wait<0>();
        __syncthreads();
        if (kt + 2 < KT) load_tiles((kt + 2) % NSTG, (kt + 2) * BK);
        gemm_step(sA, sB, kt % NSTG, wm, wn, g, tq, cc);
    }

    // epilogue: scatter-accumulate to out[token] with gate weight
    const float* bde = bd + (size_t)e * DM;
#pragma unroll
    for (int im = 0; im < 4; im++) {
        int rl = wm + im * 16 + g;
        int rg = m_base + rl;
#pragma unroll
        for (int in = 0; in < 4; in++) {
            int n = n_base + wn + in * 8 + tq * 2;
            float b0 = bde[n], b1 = bde[n + 1];
            if (rg < cnt) {
                int   t  = sTok[rl];
                float gt = sGate[rl];
                atomicAdd(&out[(size_t)t * DM + n    ], gt * (cc[im][in][0] + b0));
                atomicAdd(&out[(size_t)t * DM + n + 1], gt * (cc[im][in][1] + b1));
            }
            if (rg + 8 < cnt) {
                int   t  = sTok[rl + 8];
                float gt = sGate[rl + 8];
                atomicAdd(&out[(size_t)t * DM + n    ], gt * (cc[im][in][2] + b0));
                atomicAdd(&out[(size_t)t * DM + n + 1], gt * (cc[im][in][3] + b1));
            }
        }
    }
}

// ---------------------------------------------------------------------------
extern "C" void kernel_launch(void* const* d_in, const int* in_sizes, int n_in,
                              void* d_out, int out_size) {
    const float* x  = (const float*)d_in[0];
    const float* Wr = (const float*)d_in[1];
    const float* br = (const float*)d_in[2];
    const float* Wg = (const float*)d_in[3];
    // d_in[4] = bg
    const float* Wu = (const float*)d_in[5];
    // d_in[6] = bu
    const float* Wd = (const float*)d_in[7];
    // d_in[8] = bd
    float* out = (float*)d_out;

    cudaFuncSetAttribute(k_ffn1, cudaFuncAttributeMaxDynamicSharedMemorySize, SMEM1_BYTES);
    cudaFuncSetAttribute(k_ffn2, cudaFuncAttributeMaxDynamicSharedMemorySize, SMEM2_BYTES);

    // zero out + round x, round weights into scratch
    int n4x = T * DM / 4;
    float* xt4;
    cudaGetSymbolAddress((void**)&xt4, g_xt);
    float *wg4, *wu4, *wd4;
    cudaGetSymbolAddress((void**)&wg4, g_wg);
    cudaGetSymbolAddress((void**)&wu4, g_wu);
    cudaGetSymbolAddress((void**)&wd4, g_wd);

    k_zero_round<<<(n4x + 255) / 256, 256>>>((float4*)out, (const float4*)x, (float4*)xt4, n4x);
    int n4w = EM * DM * HM / 4;
    k_round4<<<(n4w + 255) / 256, 256>>>((const float4*)Wg, (float4*)wg4, n4w);
    k_round4<<<(n4w + 255) / 256, 256>>>((const float4*)Wu, (float4*)wu4, n4w);
    k_round4<<<(n4w + 255) / 256, 256>>>((const float4*)Wd, (float4*)wd4, n4w);

    k_router<<<T / 8, 256>>>(x, Wr, br);

    dim3 g1(T / BM, HM / 64, EM);
    k_ffn1<<<g1, 256, SMEM1_BYTES>>>((const float*)d_in[4], (const float*)d_in[6]);

    dim3 g2(T / BM, DM / BN, EM);
    k_ffn2<<<g2, 256, SMEM2_BYTES>>>((const float*)d_in[8], out);
}

// round 4
// speedup vs baseline: 1.0757x; 1.0757x over previous
#include <cuda_runtime.h>
#include <math.h>
#include <stdint.h>

// Problem constants
#define T  8192   // tokens = B*S
#define DM 1024   // model dim
#define EM 8      // experts
#define HM 4096   // hidden dim

// GEMM tiling: BM=128, BN=128 (smem cols), BK=32, 8 warps (2x4), warp tile 64x32
#define BM 128
#define BN 128
#define BK 32
#define ASTR 36    // sA row stride: bank (4g+tq) -> conflict-free
#define BSTR 136   // sB row stride: bank (8tq+g) -> conflict-free

#define SA_ELEMS (BM * ASTR)          // 4608 floats / stage
#define SB_ELEMS (BK * BSTR)          // 4352 floats / stage
#define SMEM_BYTES (2 * (SA_ELEMS + SB_ELEMS) * 4 + 2048)   // ~73.7 KB

// Device scratch (static device arrays: allowed; cudaMalloc is not)
__device__ int   g_count[EM];
__device__ int   g_tok[EM * T];
__device__ float g_gate[EM * T];
__device__ float g_xt[T * DM];           // tf32-rounded x
__device__ float g_h[EM * T * HM];       // tf32-rounded hidden activations

// ---------------------------------------------------------------------------
// helpers
// ---------------------------------------------------------------------------
__device__ __forceinline__ float f2tf32f(float x) {
    uint32_t r;
    asm("cvt.rna.tf32.f32 %0, %1;" : "=r"(r) : "f"(x));
    return __uint_as_float(r);
}
__device__ __forceinline__ uint32_t f2tf32(float x) {
    uint32_t r;
    asm("cvt.rna.tf32.f32 %0, %1;" : "=r"(r) : "f"(x));
    return r;
}

__device__ __forceinline__ void mma_tf32(float d[4], const uint32_t a[4], const uint32_t b[2]) {
    asm volatile(
        "mma.sync.aligned.m16n8k8.row.col.f32.tf32.tf32.f32 "
        "{%0,%1,%2,%3}, {%4,%5,%6,%7}, {%8,%9}, {%0,%1,%2,%3};"
        : "+f"(d[0]), "+f"(d[1]), "+f"(d[2]), "+f"(d[3])
        : "r"(a[0]), "r"(a[1]), "r"(a[2]), "r"(a[3]),
          "r"(b[0]), "r"(b[1]));
}

__device__ __forceinline__ void cp16(float* smem_ptr, const float* gptr, bool valid) {
    uint32_t sa = (uint32_t)__cvta_generic_to_shared(smem_ptr);
    int sz = valid ? 16 : 0;
    asm volatile("cp.async.cg.shared.global [%0], [%1], 16, %2;"
                 :: "r"(sa), "l"(gptr), "r"(sz));
}
__device__ __forceinline__ void cp_commit() { asm volatile("cp.async.commit_group;"); }
template <int N>
__device__ __forceinline__ void cp_wait() { asm volatile("cp.async.wait_group %0;" :: "n"(N)); }

// ---------------------------------------------------------------------------
// zero output + round x to tf32 + zero counters
// ---------------------------------------------------------------------------
__global__ void k_zero_round(float4* __restrict__ out, const float4* __restrict__ x,
                             float4* __restrict__ xt, int n4) {
    int i = blockIdx.x * blockDim.x + threadIdx.x;
    if (i < n4) {
        out[i] = make_float4(0.f, 0.f, 0.f, 0.f);
        float4 v = x[i];
        v.x = f2tf32f(v.x); v.y = f2tf32f(v.y);
        v.z = f2tf32f(v.z); v.w = f2tf32f(v.w);
        xt[i] = v;
    }
    if (i < EM) g_count[i] = 0;
}

// ---------------------------------------------------------------------------
// router: one warp per token. logits = x @ Wr + br ; top-2 ; softmax(2)
// ---------------------------------------------------------------------------
__global__ void k_router(const float* __restrict__ x,
                         const float* __restrict__ Wr,
                         const float* __restrict__ br) {
    int t    = blockIdx.x * (blockDim.x >> 5) + (threadIdx.x >> 5);
    int lane = threadIdx.x & 31;
    if (t >= T) return;

    const float* xr = x + (size_t)t * DM;
    float acc[EM];
#pragma unroll
    for (int e = 0; e < EM; e++) acc[e] = 0.0f;

    for (int d = lane; d < DM; d += 32) {
        float xv = xr[d];
        const float4 w0 = *(const float4*)(Wr + (size_t)d * EM);
        const float4 w1 = *(const float4*)(Wr + (size_t)d * EM + 4);
        acc[0] += xv * w0.x; acc[1] += xv * w0.y;
        acc[2] += xv * w0.z; acc[3] += xv * w0.w;
        acc[4] += xv * w1.x; acc[5] += xv * w1.y;
        acc[6] += xv * w1.z; acc[7] += xv * w1.w;
    }
#pragma unroll
    for (int e = 0; e < EM; e++) {
#pragma unroll
        for (int o = 16; o > 0; o >>= 1)
            acc[e] += __shfl_xor_sync(0xffffffffu, acc[e], o);
    }

    if (lane == 0) {
        float v[EM];
#pragma unroll
        for (int e = 0; e < EM; e++) v[e] = acc[e] + br[e];

        int b0 = 0; float m0 = v[0];
#pragma unroll
        for (int e = 1; e < EM; e++) if (v[e] > m0) { m0 = v[e]; b0 = e; }
        int b1 = -1; float m1 = -3.4e38f;
#pragma unroll
        for (int e = 0; e < EM; e++) {
            if (e == b0) continue;
            if (v[e] > m1) { m1 = v[e]; b1 = e; }
        }
        float p0 = 1.0f / (1.0f + expf(m1 - m0));
        float p1 = 1.0f - p0;

        int pos = atomicAdd(&g_count[b0], 1);
        g_tok[b0 * T + pos] = t;  g_gate[b0 * T + pos] = p0;
        pos = atomicAdd(&g_count[b1], 1);
        g_tok[b1 * T + pos] = t;  g_gate[b1 * T + pos] = p1;
    }
}

// ---------------------------------------------------------------------------
// shared compute step: one BK=32 k-tile, 64x32 warp tiles
// A pre-rounded (no cvt); B cvt'd inline.
// ---------------------------------------------------------------------------
#define SAI(st, r, c) sA[(st) * SA_ELEMS + (r) * ASTR + (c)]
#define SBI(st, k, c) sB[(st) * SB_ELEMS + (k) * BSTR + (c)]

__device__ __forceinline__ void gemm_step(
    const float* __restrict__ sA, const float* __restrict__ sB, int st,
    int wm, int wn, int g, int tq, float cc[4][4][4]) {
#pragma unroll
    for (int kk = 0; kk < BK; kk += 8) {
        uint32_t af[4][4];
#pragma unroll
        for (int im = 0; im < 4; im++) {
            int r = wm + im * 16 + g;
            af[im][0] = __float_as_uint(SAI(st, r,     kk + tq));
            af[im][1] = __float_as_uint(SAI(st, r + 8, kk + tq));
            af[im][2] = __float_as_uint(SAI(st, r,     kk + tq + 4));
            af[im][3] = __float_as_uint(SAI(st, r + 8, kk + tq + 4));
        }
#pragma unroll
        for (int in = 0; in < 4; in++) {
            int c = wn + in * 8 + g;
            uint32_t bf[2] = { f2tf32(SBI(st, kk + tq,     c)),
                               f2tf32(SBI(st, kk + tq + 4, c)) };
#pragma unroll
            for (int im = 0; im < 4; im++)
                mma_tf32(cc[im][in], af[im], bf);
        }
    }
}

// ---------------------------------------------------------------------------
// phase 1: h = silu(x@Wg + bg) * (x@Wu + bu)
// B tile: 128 smem cols = 64 logical H cols; cols 8q..8q+3 <- Wg, 8q+4..8q+7 <- Wu
// grid: (T/BM, HM/64, EM), 256 threads, 2-stage cp.async
// ---------------------------------------------------------------------------
__global__ __launch_bounds__(256) void k_ffn1(
    const float* __restrict__ Wg, const float* __restrict__ bg,
    const float* __restrict__ Wu, const float* __restrict__ bu) {

    const int e      = blockIdx.z;
    const int cnt    = g_count[e];
    const int m_base = blockIdx.x * BM;
    if (m_base >= cnt) return;
    const int n_base = blockIdx.y * 64;   // logical H columns

    extern __shared__ float smem[];
    float* sA   = smem;
    float* sB   = smem + 2 * SA_ELEMS;
    int*   sTok = (int*)(sB + 2 * SB_ELEMS);

    const int tid  = threadIdx.x;
    const int warp = tid >> 5, lane = tid & 31;
    const int g    = lane >> 2, tq  = lane & 3;
    const int wm   = (warp & 1) * 64;
    const int wn   = (warp >> 1) * 32;

    if (tid < BM) {
        int r = m_base + tid;
        sTok[tid] = (r < cnt) ? g_tok[e * T + r] : 0;
    }
    __syncthreads();   // gathered A loads read sTok

    float cc[4][4][4];
#pragma unroll
    for (int a = 0; a < 4; a++)
#pragma unroll
        for (int b = 0; b < 4; b++)
#pragma unroll
            for (int c = 0; c < 4; c++) cc[a][b][c] = 0.0f;

    const float* wBg = Wg + (size_t)e * DM * HM + n_base;
    const float* wBu = Wu + (size_t)e * DM * HM + n_base;

    auto load_tiles = [&](int st, int k0) {
#pragma unroll
        for (int j = 0; j < 4; j++) {          // A: 128x32 gathered rows
            int idx = tid + j * 256;
            int row = idx >> 3;
            int c4  = (idx & 7) << 2;
            cp16(&SAI(st, row, c4), g_xt + (size_t)sTok[row] * DM + k0 + c4, true);
        }
#pragma unroll
        for (int j = 0; j < 4; j++) {          // B: 32x128 interleaved Wg/Wu
            int idx = tid + j * 256;
            int kr  = idx >> 5;
            int c4  = (idx & 31) << 2;
            int q   = c4 >> 3;
            const float* src = ((c4 >> 2) & 1) ? wBu : wBg;
            cp16(&SBI(st, kr, c4), src + (size_t)(k0 + kr) * HM + 4 * q, true);
        }
        cp_commit();
    };

    load_tiles(0, 0);
    const int KT = DM / BK;   // 32
    for (int kt = 0; kt < KT; kt++) {
        int cur = kt & 1;
        if (kt + 1 < KT) { load_tiles(cur ^ 1, (kt + 1) * BK); cp_wait<1>(); }
        else             { cp_wait<0>(); }
        __syncthreads();
        gemm_step(sA, sB, cur, wm, wn, g, tq, cc);
        __syncthreads();
    }

    // epilogue: bias (own half), shuffle-exchange g<->u, silu, store tf32 h
    float* hb = g_h + (size_t)e * T * HM;
    const float* bge = bg + (size_t)e * HM;
    const float* bue = bu + (size_t)e * HM;
    const int tt = tq & 1;
    const bool is_g = (tq < 2);
#pragma unroll
    for (int im = 0; im < 4; im++) {
        int r0 = m_base + wm + im * 16 + g;
#pragma unroll
        for (int in = 0; in < 4; in++) {
            int q   = (wn >> 3) + in;
            int nl0 = n_base + 4 * q + 2 * tt;          // my 2 logical cols
            float bia0 = is_g ? bge[nl0]     : bue[nl0];
            float bia1 = is_g ? bge[nl0 + 1] : bue[nl0 + 1];
            float v0 = cc[im][in][0] + bia0, v1 = cc[im][in][1] + bia1;
            float v2 = cc[im][in][2] + bia0, v3 = cc[im][in][3] + bia1;
            float o0 = __shfl_xor_sync(0xffffffffu, v0, 2);
            float o1 = __shfl_xor_sync(0xffffffffu, v1, 2);
            float o2 = __shfl_xor_sync(0xffffffffu, v2, 2);
            float o3 = __shfl_xor_sync(0xffffffffu, v3, 2);
            if (is_g) {
                if (r0 < cnt) {
                    float2 hv;
                    hv.x = f2tf32f(v0 / (1.0f + expf(-v0)) * o0);
                    hv.y = f2tf32f(v1 / (1.0f + expf(-v1)) * o1);
                    *(float2*)(hb + (size_t)r0 * HM + nl0) = hv;
                }
                if (r0 + 8 < cnt) {
                    float2 hv;
                    hv.x = f2tf32f(v2 / (1.0f + expf(-v2)) * o2);
                    hv.y = f2tf32f(v3 / (1.0f + expf(-v3)) * o3);
                    *(float2*)(hb + (size_t)(r0 + 8) * HM + nl0) = hv;
                }
            }
        }
    }
}

// ---------------------------------------------------------------------------
// phase 2: out[tok] += gate * (h @ Wd + bd)
// grid: (T/BM, DM/BN, EM), 256 threads, 2-stage cp.async
// ---------------------------------------------------------------------------
__global__ __launch_bounds__(256) void k_ffn2(
    const float* __restrict__ Wd, const float* __restrict__ bd,
    float* __restrict__ out) {

    const int e      = blockIdx.z;
    const int cnt    = g_count[e];
    const int m_base = blockIdx.x * BM;
    if (m_base >= cnt) return;
    const int n_base = blockIdx.y * BN;

    extern __shared__ float smem[];
    float* sA    = smem;
    float* sB    = smem + 2 * SA_ELEMS;
    int*   sTok  = (int*)(sB + 2 * SB_ELEMS);
    float* sGate = (float*)(sTok + BM);

    const int tid  = threadIdx.x;
    const int warp = tid >> 5, lane = tid & 31;
    const int g    = lane >> 2, tq  = lane & 3;
    const int wm   = (warp & 1) * 64;
    const int wn   = (warp >> 1) * 32;

    if (tid < BM) {
        int r = m_base + tid;
        sTok[tid]  = (r < cnt) ? g_tok[e * T + r]  : 0;
        sGate[tid] = (r < cnt) ? g_gate[e * T + r] : 0.0f;
    }

    float cc[4][4][4];
#pragma unroll
    for (int a = 0; a < 4; a++)
#pragma unroll
        for (int b = 0; b < 4; b++)
#pragma unroll
            for (int c = 0; c < 4; c++) cc[a][b][c] = 0.0f;

    const float* hb = g_h + (size_t)e * T * HM;
    const float* wB = Wd + (size_t)e * HM * DM + n_base;

    auto load_tiles = [&](int st, int k0) {
#pragma unroll
        for (int j = 0; j < 4; j++) {          // A: 128x32 slot rows (zfill past cnt)
            int idx = tid + j * 256;
            int row = idx >> 3;
            int c4  = (idx & 7) << 2;
            bool v  = (m_base + row) < cnt;
            cp16(&SAI(st, row, c4), hb + (size_t)(m_base + row) * HM + k0 + c4, v);
        }
#pragma unroll
        for (int j = 0; j < 4; j++) {          // B: 32x128
            int idx = tid + j * 256;
            int kr  = idx >> 5;
            int c4  = (idx & 31) << 2;
            cp16(&SBI(st, kr, c4), wB + (size_t)(k0 + kr) * DM + c4, true);
        }
        cp_commit();
    };

    load_tiles(0, 0);
    const int KT = HM / BK;   // 128
    for (int kt = 0; kt < KT; kt++) {
        int cur = kt & 1;
        if (kt + 1 < KT) { load_tiles(cur ^ 1, (kt + 1) * BK); cp_wait<1>(); }
        else             { cp_wait<0>(); }
        __syncthreads();
        gemm_step(sA, sB, cur, wm, wn, g, tq, cc);
        __syncthreads();
    }

    // epilogue: scatter-accumulate to out[token] with gate weight
    const float* bde = bd + (size_t)e * DM;
#pragma unroll
    for (int im = 0; im < 4; im++) {
        int rl = wm + im * 16 + g;
        int rg = m_base + rl;
#pragma unroll
        for (int in = 0; in < 4; in++) {
            int n = n_base + wn + in * 8 + tq * 2;
            float b0 = bde[n], b1 = bde[n + 1];
            if (rg < cnt) {
                int   t  = sTok[rl];
                float gt = sGate[rl];
                atomicAdd(&out[(size_t)t * DM + n    ], gt * (cc[im][in][0] + b0));
                atomicAdd(&out[(size_t)t * DM + n + 1], gt * (cc[im][in][1] + b1));
            }
            if (rg + 8 < cnt) {
                int   t  = sTok[rl + 8];
                float gt = sGate[rl + 8];
                atomicAdd(&out[(size_t)t * DM + n    ], gt * (cc[im][in][2] + b0));
                atomicAdd(&out[(size_t)t * DM + n + 1], gt * (cc[im][in][3] + b1));
            }
        }
    }
}

// ---------------------------------------------------------------------------
extern "C" void kernel_launch(void* const* d_in, const int* in_sizes, int n_in,
                              void* d_out, int out_size) {
    const float* x  = (const float*)d_in[0];
    const float* Wr = (const float*)d_in[1];
    const float* br = (const float*)d_in[2];
    const float* Wg = (const float*)d_in[3];
    const float* bg = (const float*)d_in[4];
    const float* Wu = (const float*)d_in[5];
    const float* bu = (const float*)d_in[6];
    const float* Wd = (const float*)d_in[7];
    const float* bd = (const float*)d_in[8];
    float* out = (float*)d_out;

    cudaFuncSetAttribute(k_ffn1, cudaFuncAttributeMaxDynamicSharedMemorySize, SMEM_BYTES);
    cudaFuncSetAttribute(k_ffn2, cudaFuncAttributeMaxDynamicSharedMemorySize, SMEM_BYTES);

    float* xt4;
    cudaGetSymbolAddress((void**)&xt4, g_xt);

    int n4x = T * DM / 4;
    k_zero_round<<<(n4x + 255) / 256, 256>>>((float4*)out, (const float4*)x, (float4*)xt4, n4x);
    k_router<<<T / 8, 256>>>(x, Wr, br);

    dim3 g1(T / BM, HM / 64, EM);
    k_ffn1<<<g1, 256, SMEM_BYTES>>>(Wg, bg, Wu, bu);

    dim3 g2(T / BM, DM / BN, EM);
    k_ffn2<<<g2, 256, SMEM_BYTES>>>(Wd, bd, out);
}